// round 8
// baseline (speedup 1.0000x reference)
#include <cuda_runtime.h>

#define B_   256
#define N_   64
#define K_   12
#define D_   128
#define ROWS 16384

// ---------------- device scratch (allocation-free) ----------------
__device__ float g_uq[D_];
__device__ float g_uk[D_];
__device__ float g_c;
__device__ float g_As[(size_t)ROWS * D_];   // 8 MB combined vectors (stays in L2)
__device__ float g_Ssum[ROWS];              // attention sums

__device__ __forceinline__ float dot4(float4 a, float4 b) {
    return fmaf(a.x, b.x, fmaf(a.y, b.y, fmaf(a.z, b.z, a.w * b.w)));
}
__device__ __forceinline__ void ffma2(unsigned long long& d, unsigned long long a, unsigned long long b) {
    asm("fma.rn.f32x2 %0, %1, %2, %0;" : "+l"(d) : "l"(a), "l"(b));
}
__device__ __forceinline__ unsigned long long pack2(float x) {
    unsigned long long r;
    asm("mov.b64 %0, {%1, %1};" : "=l"(r) : "f"(x));
    return r;
}
__device__ __forceinline__ float2 unpack2(unsigned long long v) {
    float2 f;
    asm("mov.b64 {%0, %1}, %2;" : "=f"(f.x), "=f"(f.y) : "l"(v));
    return f;
}

// ---------------- prologue: uq = Wq@waq, uk = Wk@wak, c (32 blocks) --------
__global__ __launch_bounds__(128)
void gat_prologue(const float* __restrict__ Wq, const float* __restrict__ bq,
                  const float* __restrict__ Wk, const float* __restrict__ bk,
                  const float* __restrict__ waq, const float* __restrict__ wak,
                  const float* __restrict__ ba) {
    const int wid = threadIdx.x >> 5;
    const int l   = threadIdx.x & 31;
    const int r   = blockIdx.x * 4 + wid;   // row 0..127

    float4 a  = __ldg((const float4*)(Wq + r * D_) + l);
    float4 b  = __ldg((const float4*)waq + l);
    float4 c2 = __ldg((const float4*)(Wk + r * D_) + l);
    float4 d2 = __ldg((const float4*)wak + l);
    float sq = dot4(a, b);
    float sk = dot4(c2, d2);
#pragma unroll
    for (int off = 16; off; off >>= 1) {
        sq += __shfl_xor_sync(0xFFFFFFFFu, sq, off);
        sk += __shfl_xor_sync(0xFFFFFFFFu, sk, off);
    }
    if (l == 0) { g_uq[r] = sq; g_uk[r] = sk; }

    if (blockIdx.x == 0) {
        const int i = threadIdx.x;
        float p = __ldg(bq + i) * __ldg(waq + i) + __ldg(bk + i) * __ldg(wak + i);
#pragma unroll
        for (int off = 16; off; off >>= 1) p += __shfl_xor_sync(0xFFFFFFFFu, p, off);
        __shared__ float red[4];
        if (l == 0) red[wid] = p;
        __syncthreads();
        if (i == 0) g_c = red[0] + red[1] + red[2] + red[3] + __ldg(ba);
    }
}

// ---------------- kernel A: attention + weighted combine (two-pass) --------
#define A_WARPS 8
__global__ __launch_bounds__(A_WARPS * 32, 3)
void gat_attn(const float* __restrict__ nodes, const float* __restrict__ nbrs,
              const float* __restrict__ mask)
{
    const int wid = threadIdx.x >> 5;
    const int l   = threadIdx.x & 31;
    const int row = blockIdx.x * A_WARPS + wid;

    const float4 uq4 = ((const float4*)g_uq)[l];
    const float4 uk4 = ((const float4*)g_uk)[l];
    const float  cc  = g_c;

    // ---- prefetch mask: 12 uniform loads, issued before the row stream ----
    float m[K_];
    const float* mp = mask + (size_t)row * K_;
#pragma unroll
    for (int j = 0; j < K_; ++j) m[j] = __ldg(mp + j);

    // ---- pass 1: load node + neighbors, compute 14 dot partials ----
    float4 nh0 = __ldg((const float4*)(nodes + (size_t)row * D_) + l);
    const float4* np = (const float4*)(nbrs + (size_t)row * (K_ * D_));
    float kd[K_ + 1];
    float qd = dot4(nh0, uq4);
    kd[0] = dot4(nh0, uk4);
#pragma unroll
    for (int j = 0; j < K_; ++j) {
        float4 v = __ldg(np + j * 32 + l);
        kd[j + 1] = dot4(v, uk4);
    }

    // ---- butterfly reduce 14 dots across the warp ----
#pragma unroll
    for (int off = 16; off; off >>= 1) {
        qd += __shfl_xor_sync(0xFFFFFFFFu, qd, off);
#pragma unroll
        for (int j = 0; j <= K_; ++j)
            kd[j] += __shfl_xor_sync(0xFFFFFFFFu, kd[j], off);
    }

    // ---- masked LeakyReLU-exp softmax (mask in registers) ----
    const float sbase = qd + cc;
    float s = 0.f;
#pragma unroll
    for (int j = 0; j <= K_; ++j) {
        float t = kd[j] + sbase;
        t = (t >= 0.f) ? t : 0.2f * t;
        float ej = __expf(t);
        if (j) ej *= m[j - 1];
        kd[j] = ej;              // reuse kd as e
        s += ej;
    }
    const float inv = 1.f / (s + 1e-16f);
#pragma unroll
    for (int j = 0; j <= K_; ++j) kd[j] *= inv;   // normalized attention

    // ---- pass 2: reload neighbors (L1 hits) and combine ----
    float4 w = make_float4(kd[0] * nh0.x, kd[0] * nh0.y,
                           kd[0] * nh0.z, kd[0] * nh0.w);
#pragma unroll
    for (int j = 0; j < K_; ++j) {
        float4 v = __ldg(np + j * 32 + l);
        float a = kd[j + 1];
        w.x = fmaf(a, v.x, w.x);
        w.y = fmaf(a, v.y, w.y);
        w.z = fmaf(a, v.z, w.z);
        w.w = fmaf(a, v.w, w.w);
    }

    ((float4*)(g_As + (size_t)row * D_))[l] = w;
    if (l == 0) g_Ssum[row] = s * inv;
}

// ---------------- kernel B: [16384,128] x Wv[128,128] + asum*bv ------------
// 256 threads, thread tile 4x8: m_id = tid>>4 (0..15, 4 rows each),
// n_id = tid&15 (8 cols each). 2 blocks/SM -> 16 warps/SM.
#define TILE_M 64
#define B_THREADS 256
#define B_SM_FLOATS (16384 + TILE_M * 128 + 64)

__global__ __launch_bounds__(B_THREADS, 2)
void gat_gemm(const float* __restrict__ Wv, const float* __restrict__ bv,
              float* __restrict__ out)
{
    extern __shared__ float sm[];
    float* wv_s   = sm;                  // [128][128]
    float* as_s   = sm + 16384;          // [64][128]
    float* ssum_s = as_s + TILE_M * 128; // [64]

    const int tid  = threadIdx.x;
    const int row0 = blockIdx.x * TILE_M;

    {
        const float4* src = (const float4*)Wv;
        float4* dst = (float4*)wv_s;
#pragma unroll
        for (int i = tid; i < 16384 / 4; i += B_THREADS) dst[i] = src[i];
        const float4* asrc = (const float4*)(g_As + (size_t)row0 * D_);
        float4* adst = (float4*)as_s;
#pragma unroll
        for (int i = tid; i < TILE_M * 128 / 4; i += B_THREADS) adst[i] = asrc[i];
        if (tid < TILE_M) ssum_s[tid] = g_Ssum[row0 + tid];
    }
    __syncthreads();

    const int m_id = tid >> 4;   // 0..15 (4 rows each)
    const int n_id = tid & 15;   // 0..15 (8 cols each)
    const float* a_base = as_s + m_id * 4 * 128;
    const float* b_base = wv_s + n_id * 8;

    unsigned long long acc[4][4];
#pragma unroll
    for (int r = 0; r < 4; ++r)
#pragma unroll
        for (int c = 0; c < 4; ++c) acc[r][c] = 0ull;

#pragma unroll 4
    for (int k = 0; k < 128; k += 4) {
        float4 a4[4];
#pragma unroll
        for (int r = 0; r < 4; ++r)
            a4[r] = *(const float4*)(a_base + r * 128 + k);
#pragma unroll
        for (int kk = 0; kk < 4; ++kk) {
            const float* bp = b_base + (k + kk) * 128;
            ulonglong2 b01 = *(const ulonglong2*)bp;
            ulonglong2 b23 = *(const ulonglong2*)(bp + 4);
#pragma unroll
            for (int r = 0; r < 4; ++r) {
                float av = (kk == 0) ? a4[r].x : (kk == 1) ? a4[r].y
                         : (kk == 2) ? a4[r].z : a4[r].w;
                unsigned long long ap = pack2(av);
                ffma2(acc[r][0], ap, b01.x);
                ffma2(acc[r][1], ap, b01.y);
                ffma2(acc[r][2], ap, b23.x);
                ffma2(acc[r][3], ap, b23.y);
            }
        }
    }

    const float* bvp = bv + n_id * 8;
    float4 bva = __ldg((const float4*)bvp);
    float4 bvb = __ldg((const float4*)bvp + 1);
#pragma unroll
    for (int r = 0; r < 4; ++r) {
        float srow = ssum_s[m_id * 4 + r];
        float2 p0 = unpack2(acc[r][0]);
        float2 p1 = unpack2(acc[r][1]);
        float2 p2 = unpack2(acc[r][2]);
        float2 p3 = unpack2(acc[r][3]);
        float4 o0 = make_float4(fmaf(srow, bva.x, p0.x), fmaf(srow, bva.y, p0.y),
                                fmaf(srow, bva.z, p1.x), fmaf(srow, bva.w, p1.y));
        float4 o1 = make_float4(fmaf(srow, bvb.x, p2.x), fmaf(srow, bvb.y, p2.y),
                                fmaf(srow, bvb.z, p3.x), fmaf(srow, bvb.w, p3.y));
        float* op = out + (size_t)(row0 + m_id * 4 + r) * D_ + n_id * 8;
        *(float4*)op       = o0;
        *(float4*)(op + 4) = o1;
    }
}

extern "C" void kernel_launch(void* const* d_in, const int* in_sizes, int n_in,
                              void* d_out, int out_size) {
    const float* nodes = (const float*)d_in[0];
    const float* nbrs  = (const float*)d_in[1];
    const float* mask  = (const float*)d_in[2];
    const float* Wq    = (const float*)d_in[3];
    const float* bq    = (const float*)d_in[4];
    const float* Wk    = (const float*)d_in[5];
    const float* bk    = (const float*)d_in[6];
    const float* Wv    = (const float*)d_in[7];
    const float* bv    = (const float*)d_in[8];
    const float* waq   = (const float*)d_in[9];
    const float* wak   = (const float*)d_in[10];
    const float* ba    = (const float*)d_in[11];
    float* out = (float*)d_out;

    cudaFuncSetAttribute(gat_gemm, cudaFuncAttributeMaxDynamicSharedMemorySize,
                         B_SM_FLOATS * 4);

    gat_prologue<<<32, 128>>>(Wq, bq, Wk, bk, waq, wak, ba);
    gat_attn<<<ROWS / A_WARPS, A_WARPS * 32>>>(nodes, nbrs, mask);
    gat_gemm<<<ROWS / TILE_M, B_THREADS, B_SM_FLOATS * 4>>>(Wv, bv, out);
}

// round 9
// speedup vs baseline: 1.1788x; 1.1788x over previous
#include <cuda_runtime.h>

#define B_   256
#define N_   64
#define K_   12
#define D_   128
#define ROWS 16384

// ---------------- device scratch (allocation-free) ----------------
__device__ float g_uq[D_];
__device__ float g_uk[D_];
__device__ float g_c;
__device__ float g_As[(size_t)ROWS * D_];   // 8 MB combined vectors (stays in L2)
__device__ float g_Ssum[ROWS];              // attention sums

__device__ __forceinline__ float dot4(float4 a, float4 b) {
    return fmaf(a.x, b.x, fmaf(a.y, b.y, fmaf(a.z, b.z, a.w * b.w)));
}
__device__ __forceinline__ void ffma2(unsigned long long& d, unsigned long long a, unsigned long long b) {
    asm("fma.rn.f32x2 %0, %1, %2, %0;" : "+l"(d) : "l"(a), "l"(b));
}
__device__ __forceinline__ unsigned long long pack2(float x) {
    unsigned long long r;
    asm("mov.b64 %0, {%1, %1};" : "=l"(r) : "f"(x));
    return r;
}
__device__ __forceinline__ float2 unpack2(unsigned long long v) {
    float2 f;
    asm("mov.b64 {%0, %1}, %2;" : "=f"(f.x), "=f"(f.y) : "l"(v));
    return f;
}

// ---------------- prologue: uq = Wq@waq, uk = Wk@wak, c (32 blocks) --------
__global__ __launch_bounds__(128)
void gat_prologue(const float* __restrict__ Wq, const float* __restrict__ bq,
                  const float* __restrict__ Wk, const float* __restrict__ bk,
                  const float* __restrict__ waq, const float* __restrict__ wak,
                  const float* __restrict__ ba) {
    const int wid = threadIdx.x >> 5;
    const int l   = threadIdx.x & 31;
    const int r   = blockIdx.x * 4 + wid;   // row 0..127

    float4 a  = __ldg((const float4*)(Wq + r * D_) + l);
    float4 b  = __ldg((const float4*)waq + l);
    float4 c2 = __ldg((const float4*)(Wk + r * D_) + l);
    float4 d2 = __ldg((const float4*)wak + l);
    float sq = dot4(a, b);
    float sk = dot4(c2, d2);
#pragma unroll
    for (int off = 16; off; off >>= 1) {
        sq += __shfl_xor_sync(0xFFFFFFFFu, sq, off);
        sk += __shfl_xor_sync(0xFFFFFFFFu, sk, off);
    }
    if (l == 0) { g_uq[r] = sq; g_uk[r] = sk; }

    if (blockIdx.x == 0) {
        const int i = threadIdx.x;
        float p = __ldg(bq + i) * __ldg(waq + i) + __ldg(bk + i) * __ldg(wak + i);
#pragma unroll
        for (int off = 16; off; off >>= 1) p += __shfl_xor_sync(0xFFFFFFFFu, p, off);
        __shared__ float red[4];
        if (l == 0) red[wid] = p;
        __syncthreads();
        if (i == 0) g_c = red[0] + red[1] + red[2] + red[3] + __ldg(ba);
    }
}

// ---------------- kernel A: attention + weighted combine (two-pass) --------
#define A_WARPS 8
__global__ __launch_bounds__(A_WARPS * 32, 3)
void gat_attn(const float* __restrict__ nodes, const float* __restrict__ nbrs,
              const float* __restrict__ mask)
{
    const int wid = threadIdx.x >> 5;
    const int l   = threadIdx.x & 31;
    const int row = blockIdx.x * A_WARPS + wid;

    const float4 uq4 = ((const float4*)g_uq)[l];
    const float4 uk4 = ((const float4*)g_uk)[l];
    const float  cc  = g_c;

    // ---- prefetch mask: 12 uniform loads, issued before the row stream ----
    float m[K_];
    const float* mp = mask + (size_t)row * K_;
#pragma unroll
    for (int j = 0; j < K_; ++j) m[j] = __ldg(mp + j);

    // ---- pass 1: load node + neighbors, compute 14 dot partials ----
    float4 nh0 = __ldg((const float4*)(nodes + (size_t)row * D_) + l);
    const float4* np = (const float4*)(nbrs + (size_t)row * (K_ * D_));
    float kd[K_ + 1];
    float qd = dot4(nh0, uq4);
    kd[0] = dot4(nh0, uk4);
#pragma unroll
    for (int j = 0; j < K_; ++j) {
        float4 v = __ldg(np + j * 32 + l);
        kd[j + 1] = dot4(v, uk4);
    }

    // ---- butterfly reduce 14 dots across the warp ----
#pragma unroll
    for (int off = 16; off; off >>= 1) {
        qd += __shfl_xor_sync(0xFFFFFFFFu, qd, off);
#pragma unroll
        for (int j = 0; j <= K_; ++j)
            kd[j] += __shfl_xor_sync(0xFFFFFFFFu, kd[j], off);
    }

    // ---- masked LeakyReLU-exp softmax (mask in registers) ----
    const float sbase = qd + cc;
    float s = 0.f;
#pragma unroll
    for (int j = 0; j <= K_; ++j) {
        float t = kd[j] + sbase;
        t = (t >= 0.f) ? t : 0.2f * t;
        float ej = __expf(t);
        if (j) ej *= m[j - 1];
        kd[j] = ej;              // reuse kd as e
        s += ej;
    }
    const float inv = 1.f / (s + 1e-16f);
#pragma unroll
    for (int j = 0; j <= K_; ++j) kd[j] *= inv;   // normalized attention

    // ---- pass 2: reload neighbors (L1 hits) and combine ----
    float4 w = make_float4(kd[0] * nh0.x, kd[0] * nh0.y,
                           kd[0] * nh0.z, kd[0] * nh0.w);
#pragma unroll
    for (int j = 0; j < K_; ++j) {
        float4 v = __ldg(np + j * 32 + l);
        float a = kd[j + 1];
        w.x = fmaf(a, v.x, w.x);
        w.y = fmaf(a, v.y, w.y);
        w.z = fmaf(a, v.z, w.z);
        w.w = fmaf(a, v.w, w.w);
    }

    ((float4*)(g_As + (size_t)row * D_))[l] = w;
    if (l == 0) g_Ssum[row] = s * inv;
}

// ---------------- kernel B: [16384,128] x Wv[128,128] + asum*bv ------------
// TILE_M=128, 256 threads, 8x8 thread tile (16x16 threads).
// smem ~128.5KB -> 1 block/SM, grid=128 -> single wave, 8 warps/SM.
#define TILE_M 128
#define B_THREADS 256
#define B_SM_FLOATS (16384 + TILE_M * 128 + TILE_M)

__global__ __launch_bounds__(B_THREADS, 1)
void gat_gemm(const float* __restrict__ Wv, const float* __restrict__ bv,
              float* __restrict__ out)
{
    extern __shared__ float sm[];
    float* wv_s   = sm;                   // [128][128]
    float* as_s   = sm + 16384;           // [128][128]
    float* ssum_s = as_s + TILE_M * 128;  // [128]

    const int tid  = threadIdx.x;
    const int row0 = blockIdx.x * TILE_M;

    {
        const float4* src = (const float4*)Wv;
        float4* dst = (float4*)wv_s;
#pragma unroll
        for (int i = tid; i < 16384 / 4; i += B_THREADS) dst[i] = src[i];
        const float4* asrc = (const float4*)(g_As + (size_t)row0 * D_);
        float4* adst = (float4*)as_s;
#pragma unroll
        for (int i = tid; i < TILE_M * 128 / 4; i += B_THREADS) adst[i] = asrc[i];
        if (tid < TILE_M) ssum_s[tid] = g_Ssum[row0 + tid];
    }
    __syncthreads();

    // thread tile: 8 rows x 8 cols; m_id = tid>>4 (0..15), n_id = tid&15
    const int m_id = tid >> 4;
    const int n_id = tid & 15;
    const float* a_base = as_s + m_id * 8 * 128;
    const float* b_base = wv_s + n_id * 8;

    unsigned long long acc[8][4];
#pragma unroll
    for (int r = 0; r < 8; ++r)
#pragma unroll
        for (int c = 0; c < 4; ++c) acc[r][c] = 0ull;

#pragma unroll 2
    for (int k = 0; k < 128; k += 4) {
        float4 a4[8];
#pragma unroll
        for (int r = 0; r < 8; ++r)
            a4[r] = *(const float4*)(a_base + r * 128 + k);
#pragma unroll
        for (int kk = 0; kk < 4; ++kk) {
            const float* bp = b_base + (k + kk) * 128;
            ulonglong2 b01 = *(const ulonglong2*)bp;
            ulonglong2 b23 = *(const ulonglong2*)(bp + 4);
#pragma unroll
            for (int r = 0; r < 8; ++r) {
                float av = (kk == 0) ? a4[r].x : (kk == 1) ? a4[r].y
                         : (kk == 2) ? a4[r].z : a4[r].w;
                unsigned long long ap = pack2(av);
                ffma2(acc[r][0], ap, b01.x);
                ffma2(acc[r][1], ap, b01.y);
                ffma2(acc[r][2], ap, b23.x);
                ffma2(acc[r][3], ap, b23.y);
            }
        }
    }

    const float* bvp = bv + n_id * 8;
    float4 bva = __ldg((const float4*)bvp);
    float4 bvb = __ldg((const float4*)bvp + 1);
#pragma unroll
    for (int r = 0; r < 8; ++r) {
        float srow = ssum_s[m_id * 8 + r];
        float2 p0 = unpack2(acc[r][0]);
        float2 p1 = unpack2(acc[r][1]);
        float2 p2 = unpack2(acc[r][2]);
        float2 p3 = unpack2(acc[r][3]);
        float4 o0 = make_float4(fmaf(srow, bva.x, p0.x), fmaf(srow, bva.y, p0.y),
                                fmaf(srow, bva.z, p1.x), fmaf(srow, bva.w, p1.y));
        float4 o1 = make_float4(fmaf(srow, bvb.x, p2.x), fmaf(srow, bvb.y, p2.y),
                                fmaf(srow, bvb.z, p3.x), fmaf(srow, bvb.w, p3.y));
        float* op = out + (size_t)(row0 + m_id * 8 + r) * D_ + n_id * 8;
        *(float4*)op       = o0;
        *(float4*)(op + 4) = o1;
    }
}

extern "C" void kernel_launch(void* const* d_in, const int* in_sizes, int n_in,
                              void* d_out, int out_size) {
    const float* nodes = (const float*)d_in[0];
    const float* nbrs  = (const float*)d_in[1];
    const float* mask  = (const float*)d_in[2];
    const float* Wq    = (const float*)d_in[3];
    const float* bq    = (const float*)d_in[4];
    const float* Wk    = (const float*)d_in[5];
    const float* bk    = (const float*)d_in[6];
    const float* Wv    = (const float*)d_in[7];
    const float* bv    = (const float*)d_in[8];
    const float* waq   = (const float*)d_in[9];
    const float* wak   = (const float*)d_in[10];
    const float* ba    = (const float*)d_in[11];
    float* out = (float*)d_out;

    cudaFuncSetAttribute(gat_gemm, cudaFuncAttributeMaxDynamicSharedMemorySize,
                         B_SM_FLOATS * 4);

    gat_prologue<<<32, 128>>>(Wq, bq, Wk, bk, waq, wak, ba);
    gat_attn<<<ROWS / A_WARPS, A_WARPS * 32>>>(nodes, nbrs, mask);
    gat_gemm<<<ROWS / TILE_M, B_THREADS, B_SM_FLOATS * 4>>>(Wv, bv, out);
}

// round 10
// speedup vs baseline: 1.2371x; 1.0494x over previous
#include <cuda_runtime.h>

#define B_   256
#define N_   64
#define K_   12
#define D_   128
#define ROWS 16384

// ---------------- device scratch (allocation-free) ----------------
__device__ float g_uq[D_];
__device__ float g_uk[D_];
__device__ float g_c;
__device__ float g_As[(size_t)ROWS * D_];   // 8 MB combined vectors (stays in L2)
__device__ float g_Ssum[ROWS];              // attention sums

__device__ __forceinline__ float dot4(float4 a, float4 b) {
    return fmaf(a.x, b.x, fmaf(a.y, b.y, fmaf(a.z, b.z, a.w * b.w)));
}
__device__ __forceinline__ void ffma2(unsigned long long& d, unsigned long long a, unsigned long long b) {
    asm("fma.rn.f32x2 %0, %1, %2, %0;" : "+l"(d) : "l"(a), "l"(b));
}
__device__ __forceinline__ unsigned long long pack2(float x) {
    unsigned long long r;
    asm("mov.b64 %0, {%1, %1};" : "=l"(r) : "f"(x));
    return r;
}
__device__ __forceinline__ float2 unpack2(unsigned long long v) {
    float2 f;
    asm("mov.b64 {%0, %1}, %2;" : "=f"(f.x), "=f"(f.y) : "l"(v));
    return f;
}

// ---------------- prologue: uq = Wq@waq, uk = Wk@wak, c (32 blocks) --------
__global__ __launch_bounds__(128)
void gat_prologue(const float* __restrict__ Wq, const float* __restrict__ bq,
                  const float* __restrict__ Wk, const float* __restrict__ bk,
                  const float* __restrict__ waq, const float* __restrict__ wak,
                  const float* __restrict__ ba) {
    const int wid = threadIdx.x >> 5;
    const int l   = threadIdx.x & 31;
    const int r   = blockIdx.x * 4 + wid;   // row 0..127

    float4 a  = __ldg((const float4*)(Wq + r * D_) + l);
    float4 b  = __ldg((const float4*)waq + l);
    float4 c2 = __ldg((const float4*)(Wk + r * D_) + l);
    float4 d2 = __ldg((const float4*)wak + l);
    float sq = dot4(a, b);
    float sk = dot4(c2, d2);
#pragma unroll
    for (int off = 16; off; off >>= 1) {
        sq += __shfl_xor_sync(0xFFFFFFFFu, sq, off);
        sk += __shfl_xor_sync(0xFFFFFFFFu, sk, off);
    }
    if (l == 0) { g_uq[r] = sq; g_uk[r] = sk; }

    if (blockIdx.x == 0) {
        const int i = threadIdx.x;
        float p = __ldg(bq + i) * __ldg(waq + i) + __ldg(bk + i) * __ldg(wak + i);
#pragma unroll
        for (int off = 16; off; off >>= 1) p += __shfl_xor_sync(0xFFFFFFFFu, p, off);
        __shared__ float red[4];
        if (l == 0) red[wid] = p;
        __syncthreads();
        if (i == 0) g_c = red[0] + red[1] + red[2] + red[3] + __ldg(ba);
    }
}

// ---------------- kernel A: attention + weighted combine (two-pass) --------
#define A_WARPS 8
__global__ __launch_bounds__(A_WARPS * 32, 3)
void gat_attn(const float* __restrict__ nodes, const float* __restrict__ nbrs,
              const float* __restrict__ mask)
{
    const int wid = threadIdx.x >> 5;
    const int l   = threadIdx.x & 31;
    const int row = blockIdx.x * A_WARPS + wid;

    const float4 uq4 = ((const float4*)g_uq)[l];
    const float4 uk4 = ((const float4*)g_uk)[l];
    const float  cc  = g_c;

    // ---- prefetch mask: 12 uniform loads, issued before the row stream ----
    float m[K_];
    const float* mp = mask + (size_t)row * K_;
#pragma unroll
    for (int j = 0; j < K_; ++j) m[j] = __ldg(mp + j);

    // ---- pass 1: load node + neighbors, compute 14 dot partials ----
    float4 nh0 = __ldg((const float4*)(nodes + (size_t)row * D_) + l);
    const float4* np = (const float4*)(nbrs + (size_t)row * (K_ * D_));
    float kd[K_ + 1];
    float qd = dot4(nh0, uq4);
    kd[0] = dot4(nh0, uk4);
#pragma unroll
    for (int j = 0; j < K_; ++j) {
        float4 v = __ldg(np + j * 32 + l);
        kd[j + 1] = dot4(v, uk4);
    }

    // ---- butterfly reduce 14 dots across the warp ----
#pragma unroll
    for (int off = 16; off; off >>= 1) {
        qd += __shfl_xor_sync(0xFFFFFFFFu, qd, off);
#pragma unroll
        for (int j = 0; j <= K_; ++j)
            kd[j] += __shfl_xor_sync(0xFFFFFFFFu, kd[j], off);
    }

    // ---- masked LeakyReLU-exp softmax (mask in registers) ----
    const float sbase = qd + cc;
    float s = 0.f;
#pragma unroll
    for (int j = 0; j <= K_; ++j) {
        float t = kd[j] + sbase;
        t = (t >= 0.f) ? t : 0.2f * t;
        float ej = __expf(t);
        if (j) ej *= m[j - 1];
        kd[j] = ej;              // reuse kd as e
        s += ej;
    }
    const float inv = 1.f / (s + 1e-16f);
#pragma unroll
    for (int j = 0; j <= K_; ++j) kd[j] *= inv;   // normalized attention

    // ---- pass 2: reload neighbors (L1 hits) and combine ----
    float4 w = make_float4(kd[0] * nh0.x, kd[0] * nh0.y,
                           kd[0] * nh0.z, kd[0] * nh0.w);
#pragma unroll
    for (int j = 0; j < K_; ++j) {
        float4 v = __ldg(np + j * 32 + l);
        float a = kd[j + 1];
        w.x = fmaf(a, v.x, w.x);
        w.y = fmaf(a, v.y, w.y);
        w.z = fmaf(a, v.z, w.z);
        w.w = fmaf(a, v.w, w.w);
    }

    ((float4*)(g_As + (size_t)row * D_))[l] = w;
    if (l == 0) g_Ssum[row] = s * inv;
}

// ---------------- kernel B: [16384,128] x Wv[128,128] + asum*bv ------------
// TILE_M=128, 512 threads. Warp = 8 rows x 128 cols; lane owns 4 cols.
// Per-warp LDS per 4-k: 8 broadcast A + 4 coalesced B vs 128 FFMA2-issue cyc.
// smem ~128.5KB -> 1 block/SM, 16 warps/SM, grid=128 single wave.
#define TILE_M 128
#define B_THREADS 512
#define B_SM_FLOATS (16384 + TILE_M * 128 + TILE_M)

__global__ __launch_bounds__(B_THREADS, 1)
void gat_gemm(const float* __restrict__ Wv, const float* __restrict__ bv,
              float* __restrict__ out)
{
    extern __shared__ float sm[];
    float* wv_s   = sm;                   // [128][128]
    float* as_s   = sm + 16384;           // [128][128]
    float* ssum_s = as_s + TILE_M * 128;  // [128]

    const int tid  = threadIdx.x;
    const int row0 = blockIdx.x * TILE_M;

    {
        const float4* src = (const float4*)Wv;
        float4* dst = (float4*)wv_s;
#pragma unroll
        for (int i = tid; i < 16384 / 4; i += B_THREADS) dst[i] = src[i];
        const float4* asrc = (const float4*)(g_As + (size_t)row0 * D_);
        float4* adst = (float4*)as_s;
#pragma unroll
        for (int i = tid; i < TILE_M * 128 / 4; i += B_THREADS) adst[i] = asrc[i];
        if (tid < TILE_M) ssum_s[tid] = g_Ssum[row0 + tid];
    }
    __syncthreads();

    const int lane = tid & 31;    // column group: cols lane*4 .. lane*4+3
    const int wm   = tid >> 5;    // warp id 0..15: rows wm*8 .. wm*8+7
    const float* a_base = as_s + wm * 8 * 128;
    const float* b_base = wv_s + lane * 4;

    unsigned long long acc[8][2];
#pragma unroll
    for (int r = 0; r < 8; ++r) { acc[r][0] = 0ull; acc[r][1] = 0ull; }

#pragma unroll 2
    for (int k = 0; k < 128; k += 4) {
        float4 a4[8];
#pragma unroll
        for (int r = 0; r < 8; ++r)
            a4[r] = *(const float4*)(a_base + r * 128 + k);   // broadcast LDS
#pragma unroll
        for (int kk = 0; kk < 4; ++kk) {
            ulonglong2 b = *(const ulonglong2*)(b_base + (k + kk) * 128);
#pragma unroll
            for (int r = 0; r < 8; ++r) {
                float av = (kk == 0) ? a4[r].x : (kk == 1) ? a4[r].y
                         : (kk == 2) ? a4[r].z : a4[r].w;
                unsigned long long ap = pack2(av);
                ffma2(acc[r][0], ap, b.x);
                ffma2(acc[r][1], ap, b.y);
            }
        }
    }

    // epilogue: + asum * bv, store (warp writes 8 rows x 512B, coalesced)
    float4 bv4 = __ldg((const float4*)(bv + lane * 4));
#pragma unroll
    for (int r = 0; r < 8; ++r) {
        float srow = ssum_s[wm * 8 + r];
        float2 p0 = unpack2(acc[r][0]);
        float2 p1 = unpack2(acc[r][1]);
        float4 o = make_float4(fmaf(srow, bv4.x, p0.x), fmaf(srow, bv4.y, p0.y),
                               fmaf(srow, bv4.z, p1.x), fmaf(srow, bv4.w, p1.y));
        *(float4*)(out + (size_t)(row0 + wm * 8 + r) * D_ + lane * 4) = o;
    }
}

extern "C" void kernel_launch(void* const* d_in, const int* in_sizes, int n_in,
                              void* d_out, int out_size) {
    const float* nodes = (const float*)d_in[0];
    const float* nbrs  = (const float*)d_in[1];
    const float* mask  = (const float*)d_in[2];
    const float* Wq    = (const float*)d_in[3];
    const float* bq    = (const float*)d_in[4];
    const float* Wk    = (const float*)d_in[5];
    const float* bk    = (const float*)d_in[6];
    const float* Wv    = (const float*)d_in[7];
    const float* bv    = (const float*)d_in[8];
    const float* waq   = (const float*)d_in[9];
    const float* wak   = (const float*)d_in[10];
    const float* ba    = (const float*)d_in[11];
    float* out = (float*)d_out;

    cudaFuncSetAttribute(gat_gemm, cudaFuncAttributeMaxDynamicSharedMemorySize,
                         B_SM_FLOATS * 4);

    gat_prologue<<<32, 128>>>(Wq, bq, Wk, bk, waq, wak, ba);
    gat_attn<<<ROWS / A_WARPS, A_WARPS * 32>>>(nodes, nbrs, mask);
    gat_gemm<<<ROWS / TILE_M, B_THREADS, B_SM_FLOATS * 4>>>(Wv, bv, out);
}

// round 11
// speedup vs baseline: 1.3099x; 1.0589x over previous
#include <cuda_runtime.h>

#define B_   256
#define N_   64
#define K_   12
#define D_   128
#define ROWS 16384

// ---------------- device scratch (allocation-free) ----------------
__device__ float g_uq[D_];
__device__ float g_uk[D_];
__device__ float g_c;

__device__ __forceinline__ float dot4(float4 a, float4 b) {
    return fmaf(a.x, b.x, fmaf(a.y, b.y, fmaf(a.z, b.z, a.w * b.w)));
}
__device__ __forceinline__ void ffma2(unsigned long long& d, unsigned long long a, unsigned long long b) {
    asm("fma.rn.f32x2 %0, %1, %2, %0;" : "+l"(d) : "l"(a), "l"(b));
}
__device__ __forceinline__ unsigned long long pack2(float x) {
    unsigned long long r;
    asm("mov.b64 %0, {%1, %1};" : "=l"(r) : "f"(x));
    return r;
}
__device__ __forceinline__ float2 unpack2(unsigned long long v) {
    float2 f;
    asm("mov.b64 {%0, %1}, %2;" : "=f"(f.x), "=f"(f.y) : "l"(v));
    return f;
}

// ---------------- prologue: uq = Wq@waq, uk = Wk@wak, c (32 blocks) --------
__global__ __launch_bounds__(128)
void gat_prologue(const float* __restrict__ Wq, const float* __restrict__ bq,
                  const float* __restrict__ Wk, const float* __restrict__ bk,
                  const float* __restrict__ waq, const float* __restrict__ wak,
                  const float* __restrict__ ba) {
    const int wid = threadIdx.x >> 5;
    const int l   = threadIdx.x & 31;
    const int r   = blockIdx.x * 4 + wid;   // row 0..127

    float4 a  = __ldg((const float4*)(Wq + r * D_) + l);
    float4 b  = __ldg((const float4*)waq + l);
    float4 c2 = __ldg((const float4*)(Wk + r * D_) + l);
    float4 d2 = __ldg((const float4*)wak + l);
    float sq = dot4(a, b);
    float sk = dot4(c2, d2);
#pragma unroll
    for (int off = 16; off; off >>= 1) {
        sq += __shfl_xor_sync(0xFFFFFFFFu, sq, off);
        sk += __shfl_xor_sync(0xFFFFFFFFu, sk, off);
    }
    if (l == 0) { g_uq[r] = sq; g_uk[r] = sk; }

    if (blockIdx.x == 0) {
        const int i = threadIdx.x;
        float p = __ldg(bq + i) * __ldg(waq + i) + __ldg(bk + i) * __ldg(wak + i);
#pragma unroll
        for (int off = 16; off; off >>= 1) p += __shfl_xor_sync(0xFFFFFFFFu, p, off);
        __shared__ float red[4];
        if (l == 0) red[wid] = p;
        __syncthreads();
        if (i == 0) g_c = red[0] + red[1] + red[2] + red[3] + __ldg(ba);
    }
}

// ---------------- fused kernel: attention + combine + GEMM -----------------
// 128 blocks x 512 threads. Block owns 128 rows; warp wm owns rows wm*8..+7.
// Per warp: attn(8 rows) -> as_s slice -> GEMM(8 rows x 128 cols).
// No block sync between phases (warp-private As slice); one syncthreads for Wv.
#define F_THREADS 512
#define F_TILE    128
#define F_SM_FLOATS (16384 + F_TILE * 128)

__global__ __launch_bounds__(F_THREADS, 1)
void gat_fused(const float* __restrict__ nodes, const float* __restrict__ nbrs,
               const float* __restrict__ mask,
               const float* __restrict__ Wv, const float* __restrict__ bv,
               float* __restrict__ out)
{
    extern __shared__ float sm[];
    float* wv_s = sm;              // [128][128]
    float* as_s = sm + 16384;      // [128][128]

    const int tid  = threadIdx.x;
    const int lane = tid & 31;
    const int wm   = tid >> 5;     // 0..15
    const int row0 = blockIdx.x * F_TILE;

    // ---- issue Wv -> shared early; latency hides under the attn phase ----
    {
        const float4* src = (const float4*)Wv;
        float4* dst = (float4*)wv_s;
#pragma unroll
        for (int i = tid; i < 16384 / 4; i += F_THREADS) dst[i] = src[i];
    }

    const float4 uq4 = ((const float4*)g_uq)[lane];
    const float4 uk4 = ((const float4*)g_uk)[lane];
    const float  cc  = g_c;

    float* aw = as_s + wm * 8 * 128;   // warp-private As slice
    float  asum[8];

    // =================== phase 1: attention for 8 rows ===================
#pragma unroll 1
    for (int r = 0; r < 8; ++r) {
        const int row = row0 + wm * 8 + r;

        // mask prefetch (12 uniform loads)
        float m[K_];
        const float* mp = mask + (size_t)row * K_;
#pragma unroll
        for (int j = 0; j < K_; ++j) m[j] = __ldg(mp + j);

        // load node + 12 neighbors; 14 dot partials
        float4 nh0 = __ldg((const float4*)(nodes + (size_t)row * D_) + lane);
        const float4* np = (const float4*)(nbrs + (size_t)row * (K_ * D_));
        float kd[K_ + 1];
        float qd = dot4(nh0, uq4);
        kd[0] = dot4(nh0, uk4);
#pragma unroll
        for (int j = 0; j < K_; ++j) {
            float4 v = __ldg(np + j * 32 + lane);
            kd[j + 1] = dot4(v, uk4);
        }

        // butterfly reduce
#pragma unroll
        for (int off = 16; off; off >>= 1) {
            qd += __shfl_xor_sync(0xFFFFFFFFu, qd, off);
#pragma unroll
            for (int j = 0; j <= K_; ++j)
                kd[j] += __shfl_xor_sync(0xFFFFFFFFu, kd[j], off);
        }

        // masked LeakyReLU-exp softmax
        const float sbase = qd + cc;
        float s = 0.f;
#pragma unroll
        for (int j = 0; j <= K_; ++j) {
            float t = kd[j] + sbase;
            t = (t >= 0.f) ? t : 0.2f * t;
            float ej = __expf(t);
            if (j) ej *= m[j - 1];
            kd[j] = ej;
            s += ej;
        }
        const float inv = 1.f / (s + 1e-16f);
#pragma unroll
        for (int j = 0; j <= K_; ++j) kd[j] *= inv;

        // pass 2: reload neighbors (L1 hits) and combine
        float4 w = make_float4(kd[0] * nh0.x, kd[0] * nh0.y,
                               kd[0] * nh0.z, kd[0] * nh0.w);
#pragma unroll
        for (int j = 0; j < K_; ++j) {
            float4 v = __ldg(np + j * 32 + lane);
            float a = kd[j + 1];
            w.x = fmaf(a, v.x, w.x);
            w.y = fmaf(a, v.y, w.y);
            w.z = fmaf(a, v.z, w.z);
            w.w = fmaf(a, v.w, w.w);
        }

        ((float4*)(aw + r * 128))[lane] = w;
        asum[r] = s * inv;
    }

    __syncthreads();   // Wv stores complete (as_s slice is warp-private)

    // =================== phase 2: GEMM 8 rows x 128 cols ===================
    const float* b_base = wv_s + lane * 4;

    unsigned long long acc[8][2];
#pragma unroll
    for (int r = 0; r < 8; ++r) { acc[r][0] = 0ull; acc[r][1] = 0ull; }

#pragma unroll 2
    for (int k = 0; k < 128; k += 4) {
        float4 a4[8];
#pragma unroll
        for (int r = 0; r < 8; ++r)
            a4[r] = *(const float4*)(aw + r * 128 + k);   // broadcast LDS
#pragma unroll
        for (int kk = 0; kk < 4; ++kk) {
            ulonglong2 b = *(const ulonglong2*)(b_base + (k + kk) * 128);
#pragma unroll
            for (int r = 0; r < 8; ++r) {
                float av = (kk == 0) ? a4[r].x : (kk == 1) ? a4[r].y
                         : (kk == 2) ? a4[r].z : a4[r].w;
                unsigned long long ap = pack2(av);
                ffma2(acc[r][0], ap, b.x);
                ffma2(acc[r][1], ap, b.y);
            }
        }
    }

    // epilogue: + asum * bv, coalesced stores
    float4 bv4 = __ldg((const float4*)(bv + lane * 4));
#pragma unroll
    for (int r = 0; r < 8; ++r) {
        float2 p0 = unpack2(acc[r][0]);
        float2 p1 = unpack2(acc[r][1]);
        float4 o = make_float4(fmaf(asum[r], bv4.x, p0.x),
                               fmaf(asum[r], bv4.y, p0.y),
                               fmaf(asum[r], bv4.z, p1.x),
                               fmaf(asum[r], bv4.w, p1.y));
        *(float4*)(out + (size_t)(row0 + wm * 8 + r) * D_ + lane * 4) = o;
    }
}

extern "C" void kernel_launch(void* const* d_in, const int* in_sizes, int n_in,
                              void* d_out, int out_size) {
    const float* nodes = (const float*)d_in[0];
    const float* nbrs  = (const float*)d_in[1];
    const float* mask  = (const float*)d_in[2];
    const float* Wq    = (const float*)d_in[3];
    const float* bq    = (const float*)d_in[4];
    const float* Wk    = (const float*)d_in[5];
    const float* bk    = (const float*)d_in[6];
    const float* Wv    = (const float*)d_in[7];
    const float* bv    = (const float*)d_in[8];
    const float* waq   = (const float*)d_in[9];
    const float* wak   = (const float*)d_in[10];
    const float* ba    = (const float*)d_in[11];
    float* out = (float*)d_out;

    cudaFuncSetAttribute(gat_fused, cudaFuncAttributeMaxDynamicSharedMemorySize,
                         F_SM_FLOATS * 4);

    gat_prologue<<<32, 128>>>(Wq, bq, Wk, bk, waq, wak, ba);
    gat_fused<<<ROWS / F_TILE, F_THREADS, F_SM_FLOATS * 4>>>(nodes, nbrs, mask,
                                                             Wv, bv, out);
}

// round 12
// speedup vs baseline: 1.3634x; 1.0409x over previous
#include <cuda_runtime.h>

#define B_   256
#define N_   64
#define K_   12
#define D_   128
#define ROWS 16384

__device__ __forceinline__ float dot4(float4 a, float4 b) {
    return fmaf(a.x, b.x, fmaf(a.y, b.y, fmaf(a.z, b.z, a.w * b.w)));
}
__device__ __forceinline__ void ffma2(unsigned long long& d, unsigned long long a, unsigned long long b) {
    asm("fma.rn.f32x2 %0, %1, %2, %0;" : "+l"(d) : "l"(a), "l"(b));
}
__device__ __forceinline__ unsigned long long pack2(float x) {
    unsigned long long r;
    asm("mov.b64 %0, {%1, %1};" : "=l"(r) : "f"(x));
    return r;
}
__device__ __forceinline__ float2 unpack2(unsigned long long v) {
    float2 f;
    asm("mov.b64 {%0, %1}, %2;" : "=f"(f.x), "=f"(f.y) : "l"(v));
    return f;
}
__device__ __forceinline__ void prefetchL1(const void* p) {
    asm volatile("prefetch.global.L1 [%0];" :: "l"(p));
}

// ---------------- single fused kernel ---------------------------------------
// 128 blocks x 512 threads, 1 block/SM (smem ~129KB), single wave.
// Per block: [Wv->smem  ||  redundant uq/uk/c compute] -> syncthreads ->
// per warp: 8 rows of (prefetch-pipelined attention + combine) -> GEMM 8x128.
#define F_THREADS 512
#define F_TILE    128
// floats: Wv 16384 + As 16384 + uq 128 + uk 128 + c 4
#define F_SM_FLOATS (16384 + 16384 + 128 + 128 + 4)

__global__ __launch_bounds__(F_THREADS, 1)
void gat_fused(const float* __restrict__ nodes, const float* __restrict__ nbrs,
               const float* __restrict__ mask,
               const float* __restrict__ Wq, const float* __restrict__ bq,
               const float* __restrict__ Wk, const float* __restrict__ bk,
               const float* __restrict__ Wv, const float* __restrict__ bv,
               const float* __restrict__ waq, const float* __restrict__ wak,
               const float* __restrict__ ba,
               float* __restrict__ out)
{
    extern __shared__ float sm[];
    float* wv_s = sm;                      // [128][128]
    float* as_s = sm + 16384;              // [128][128]
    float* uq_s = as_s + 16384;            // [128]
    float* uk_s = uq_s + 128;              // [128]
    float* c_s  = uk_s + 128;              // [1]

    const int tid  = threadIdx.x;
    const int lane = tid & 31;
    const int wm   = tid >> 5;             // 0..15
    const int row0 = blockIdx.x * F_TILE;

    // ---- Wv -> shared (issued first; drains by the syncthreads) ----
    {
        const float4* src = (const float4*)Wv;
        float4* dst = (float4*)wv_s;
#pragma unroll
        for (int i = tid; i < 16384 / 4; i += F_THREADS) dst[i] = src[i];
    }

    // ---- redundant per-block prologue: uq = Wq@waq, uk = Wk@wak, c ----
    {
        float4 waq4 = __ldg((const float4*)waq + lane);
        float4 wak4 = __ldg((const float4*)wak + lane);
#pragma unroll
        for (int i = 0; i < 8; ++i) {
            const int r = wm * 8 + i;      // 0..127
            float4 a  = __ldg((const float4*)(Wq + r * D_) + lane);
            float4 k4 = __ldg((const float4*)(Wk + r * D_) + lane);
            float sq = dot4(a, waq4);
            float sk = dot4(k4, wak4);
#pragma unroll
            for (int off = 16; off; off >>= 1) {
                sq += __shfl_xor_sync(0xFFFFFFFFu, sq, off);
                sk += __shfl_xor_sync(0xFFFFFFFFu, sk, off);
            }
            if (lane == 0) { uq_s[r] = sq; uk_s[r] = sk; }
        }
        if (wm == 0) {
            float4 xq = __ldg((const float4*)bq + lane);
            float4 xk = __ldg((const float4*)bk + lane);
            float p = dot4(xq, waq4) + dot4(xk, wak4);
#pragma unroll
            for (int off = 16; off; off >>= 1)
                p += __shfl_xor_sync(0xFFFFFFFFu, p, off);
            if (lane == 0) c_s[0] = p + __ldg(ba);
        }
    }
    __syncthreads();   // Wv + uq/uk/c ready

    const float4 uq4 = ((const float4*)uq_s)[lane];
    const float4 uk4 = ((const float4*)uk_s)[lane];
    const float  cc  = c_s[0];

    float* aw = as_s + wm * 8 * 128;       // warp-private As slice
    float  asum[8];

    // =================== phase 1: attention for 8 rows (pipelined) ========
#pragma unroll 1
    for (int r = 0; r < 8; ++r) {
        const int row = row0 + wm * 8 + r;

        // mask prefetch (12 uniform loads)
        float m[K_];
        const float* mp = mask + (size_t)row * K_;
#pragma unroll
        for (int j = 0; j < K_; ++j) m[j] = __ldg(mp + j);

        // pass 1: load node + 12 neighbors; 14 dot partials
        float4 nh0 = __ldg((const float4*)(nodes + (size_t)row * D_) + lane);
        const float4* np = (const float4*)(nbrs + (size_t)row * (K_ * D_));
        float kd[K_ + 1];
        float qd = dot4(nh0, uq4);
        kd[0] = dot4(nh0, uk4);
#pragma unroll
        for (int j = 0; j < K_; ++j) {
            float4 v = __ldg(np + j * 32 + lane);
            kd[j + 1] = dot4(v, uk4);
        }

        // software pipeline: pull row r+1's lines into L1 while we compute
        if (r < 7) {
            const float4* np1 = np + K_ * 32;                 // next row's nbrs
#pragma unroll
            for (int j = 0; j < K_; ++j) prefetchL1(np1 + j * 32 + lane);
            prefetchL1((const float4*)(nodes + (size_t)(row + 1) * D_) + lane);
            if (lane == 0) prefetchL1(mp + K_);
        }

        // butterfly reduce 14 dots
#pragma unroll
        for (int off = 16; off; off >>= 1) {
            qd += __shfl_xor_sync(0xFFFFFFFFu, qd, off);
#pragma unroll
            for (int j = 0; j <= K_; ++j)
                kd[j] += __shfl_xor_sync(0xFFFFFFFFu, kd[j], off);
        }

        // masked LeakyReLU-exp softmax
        const float sbase = qd + cc;
        float s = 0.f;
#pragma unroll
        for (int j = 0; j <= K_; ++j) {
            float t = kd[j] + sbase;
            t = (t >= 0.f) ? t : 0.2f * t;
            float ej = __expf(t);
            if (j) ej *= m[j - 1];
            kd[j] = ej;
            s += ej;
        }
        const float inv = 1.f / (s + 1e-16f);
#pragma unroll
        for (int j = 0; j <= K_; ++j) kd[j] *= inv;

        // pass 2: reload neighbors (L1 hits) and combine
        float4 w = make_float4(kd[0] * nh0.x, kd[0] * nh0.y,
                               kd[0] * nh0.z, kd[0] * nh0.w);
#pragma unroll
        for (int j = 0; j < K_; ++j) {
            float4 v = __ldg(np + j * 32 + lane);
            float a = kd[j + 1];
            w.x = fmaf(a, v.x, w.x);
            w.y = fmaf(a, v.y, w.y);
            w.z = fmaf(a, v.z, w.z);
            w.w = fmaf(a, v.w, w.w);
        }

        ((float4*)(aw + r * 128))[lane] = w;
        asum[r] = s * inv;
    }

    __syncwarp();      // as_s slice visible within the warp

    // =================== phase 2: GEMM 8 rows x 128 cols ===================
    const float* b_base = wv_s + lane * 4;

    unsigned long long acc[8][2];
#pragma unroll
    for (int r = 0; r < 8; ++r) { acc[r][0] = 0ull; acc[r][1] = 0ull; }

#pragma unroll 2
    for (int k = 0; k < 128; k += 4) {
        float4 a4[8];
#pragma unroll
        for (int r = 0; r < 8; ++r)
            a4[r] = *(const float4*)(aw + r * 128 + k);   // broadcast LDS
#pragma unroll
        for (int kk = 0; kk < 4; ++kk) {
            ulonglong2 b = *(const ulonglong2*)(b_base + (k + kk) * 128);
#pragma unroll
            for (int r = 0; r < 8; ++r) {
                float av = (kk == 0) ? a4[r].x : (kk == 1) ? a4[r].y
                         : (kk == 2) ? a4[r].z : a4[r].w;
                unsigned long long ap = pack2(av);
                ffma2(acc[r][0], ap, b.x);
                ffma2(acc[r][1], ap, b.y);
            }
        }
    }

    // epilogue: + asum * bv, coalesced stores
    float4 bv4 = __ldg((const float4*)(bv + lane * 4));
#pragma unroll
    for (int r = 0; r < 8; ++r) {
        float2 p0 = unpack2(acc[r][0]);
        float2 p1 = unpack2(acc[r][1]);
        float4 o = make_float4(fmaf(asum[r], bv4.x, p0.x),
                               fmaf(asum[r], bv4.y, p0.y),
                               fmaf(asum[r], bv4.z, p1.x),
                               fmaf(asum[r], bv4.w, p1.y));
        *(float4*)(out + (size_t)(row0 + wm * 8 + r) * D_ + lane * 4) = o;
    }
}

extern "C" void kernel_launch(void* const* d_in, const int* in_sizes, int n_in,
                              void* d_out, int out_size) {
    const float* nodes = (const float*)d_in[0];
    const float* nbrs  = (const float*)d_in[1];
    const float* mask  = (const float*)d_in[2];
    const float* Wq    = (const float*)d_in[3];
    const float* bq    = (const float*)d_in[4];
    const float* Wk    = (const float*)d_in[5];
    const float* bk    = (const float*)d_in[6];
    const float* Wv    = (const float*)d_in[7];
    const float* bv    = (const float*)d_in[8];
    const float* waq   = (const float*)d_in[9];
    const float* wak   = (const float*)d_in[10];
    const float* ba    = (const float*)d_in[11];
    float* out = (float*)d_out;

    cudaFuncSetAttribute(gat_fused, cudaFuncAttributeMaxDynamicSharedMemorySize,
                         F_SM_FLOATS * 4);

    gat_fused<<<ROWS / F_TILE, F_THREADS, F_SM_FLOATS * 4>>>(
        nodes, nbrs, mask, Wq, bq, Wk, bk, Wv, bv, waq, wak, ba, out);
}